// round 14
// baseline (speedup 1.0000x reference)
#include <cuda_runtime.h>
#include <cuda_bf16.h>
#include <math.h>
#include <stdint.h>

// ---------------------------------------------------------------------------
// Qwen3 attention layer.  mma.sync tf32 for GEMMs AND flash attention.
//   T=2048, D=4096, H=32, KV=8, HD=128
// ---------------------------------------------------------------------------
#define T_      2048
#define D_      4096
#define H_      32
#define KV_     8
#define HD_     128
#define QKV_N   ((H_ + 2 * KV_) * HD_)   // 6144

// scratch (no cudaMalloc allowed)
__device__ __align__(128) float g_qkv  [T_ * QKV_N];       // 50 MB
__device__ __align__(128) float g_attn [T_ * H_ * HD_];    // 33 MB
__device__ __align__(128) float g_wqkvT[QKV_N * D_];       // 100 MB ([N,K], tf32)
__device__ __align__(128) float g_woT  [D_ * D_];          // 67 MB  ([N,K], tf32)
__device__ __align__(128) float g_hidR [T_ * D_];          // 32 MB  (tf32)
__device__ __align__(128) float g_vT   [KV_ * HD_ * T_];   // 8 MB   (V^T, tf32)

// ---------------------------------------------------------------------------
// helpers
// ---------------------------------------------------------------------------
__device__ __forceinline__ uint32_t su32(const void* p) {
    return (uint32_t)__cvta_generic_to_shared(p);
}
__device__ __forceinline__ float tf32r(float x) {
    uint32_t r;
    asm("cvt.rna.tf32.f32 %0, %1;" : "=r"(r) : "f"(x));
    return __uint_as_float(r);
}
__device__ __forceinline__ void cp16(uint32_t dst, const float* src) {
    asm volatile("cp.async.cg.shared.global [%0], [%1], 16;"
                 :: "r"(dst), "l"(src) : "memory");
}
__device__ __forceinline__ void mma8(float* d, const uint32_t* a, const uint32_t* b) {
    asm volatile(
        "mma.sync.aligned.m16n8k8.row.col.f32.tf32.tf32.f32 "
        "{%0,%1,%2,%3}, {%4,%5,%6,%7}, {%8,%9}, {%0,%1,%2,%3};"
        : "+f"(d[0]), "+f"(d[1]), "+f"(d[2]), "+f"(d[3])
        : "r"(a[0]), "r"(a[1]), "r"(a[2]), "r"(a[3]), "r"(b[0]), "r"(b[1]));
}

// ---------------------------------------------------------------------------
// tf32 GEMM via mma.sync: C[M,N] = A[M,K] @ Bt[N,K]^T
// CTA tile 256x128 (L2-traffic reduction: the GEMM is L2-BW bound at 128x128
// — 64KB/SM-chunk over ~1780cyc = ~5.4KB/cyc chip ≈ LTS cap).  BK=32,
// 3-stage cp.async with the proven unconditional-commit + wait_group 1
// discipline.  8 warps (4x2) of 64x64 warp tiles, 256 threads, 1 CTA/SM.
// grid = (M/256, N/128)
// ---------------------------------------------------------------------------
#define GSTRIDE 36
#define ATILE   (256 * GSTRIDE)            // floats
#define BTILE   (128 * GSTRIDE)
#define GSTAGE  (ATILE + BTILE)            // 13824 floats = 55296 B
#define GNST    3
#define GEMM_SMEM (GNST * GSTAGE * 4)      // 162 KB, 1 CTA/SM

__device__ __forceinline__ void g_load_chunk(uint32_t sA, uint32_t sB,
                                             const float* __restrict__ Arow,
                                             const float* __restrict__ Brow,
                                             int K, int k0, int tid) {
    // A: 256 rows x 32 floats = 2048 x 16B chunks
#pragma unroll
    for (int i = 0; i < 8; i++) {
        int idx = i * 256 + tid;
        int r = idx >> 3, ch = idx & 7;
        cp16(sA + r * (GSTRIDE * 4) + ch * 16,
             Arow + (size_t)r * K + k0 + ch * 4);
    }
    // B: 128 rows x 32 floats = 1024 x 16B chunks
#pragma unroll
    for (int i = 0; i < 4; i++) {
        int idx = i * 256 + tid;
        int r = idx >> 3, ch = idx & 7;
        cp16(sB + r * (GSTRIDE * 4) + ch * 16,
             Brow + (size_t)r * K + k0 + ch * 4);
    }
}

__global__ __launch_bounds__(256, 1)
void gemm_tf32_kernel(const float* __restrict__ A, const float* __restrict__ Bt,
                      float* __restrict__ C, int K, int N) {
    extern __shared__ float gsm[];

    const int tid  = threadIdx.x;
    const int wid  = tid >> 5, lane = tid & 31;
    const int wm   = wid >> 1;             // 0..3 (64-row slab)
    const int wn   = wid & 1;              // 0..1 (64-col slab)
    const int m0   = blockIdx.x * 256;
    const int n0   = blockIdx.y * 128;

    const float* Arow = A  + (size_t)m0 * K;
    const float* Brow = Bt + (size_t)n0 * K;
    const uint32_t sb = su32(gsm);

    float acc[4][8][4];                    // 64x64 warp tile
#pragma unroll
    for (int mt = 0; mt < 4; mt++)
#pragma unroll
        for (int nt = 0; nt < 8; nt++)
#pragma unroll
            for (int r = 0; r < 4; r++) acc[mt][nt][r] = 0.f;

    const int NC = K >> 5;

    // prologue: stages 0,1 (chunks 0,1)
#pragma unroll
    for (int s = 0; s < GNST - 1; s++) {
        g_load_chunk(sb + s * (GSTAGE * 4), sb + s * (GSTAGE * 4) + ATILE * 4,
                     Arow, Brow, K, s * 32, tid);
        asm volatile("cp.async.commit_group;" ::: "memory");
    }

    for (int c = 0; c < NC; c++) {
        asm volatile("cp.async.wait_group 1;" ::: "memory");
        __syncthreads();

        const int cl = c + 2;
        if (cl < NC) {
            const int sl = cl % GNST;
            g_load_chunk(sb + sl * (GSTAGE * 4),
                         sb + sl * (GSTAGE * 4) + ATILE * 4,
                         Arow, Brow, K, cl * 32, tid);
        }
        // unconditional commit: empty groups near the tail keep the
        // outstanding-count invariant for wait_group 1 (R8 bug class).
        asm volatile("cp.async.commit_group;" ::: "memory");

        const int s = c % GNST;
        const float* As = gsm + s * GSTAGE;
        const float* Bs = As + ATILE;
        const float* ab = As + (wm * 64 + (lane >> 2)) * GSTRIDE + (lane & 3);
        const float* bb = Bs + (wn * 64 + (lane >> 2)) * GSTRIDE + (lane & 3);

#pragma unroll
        for (int ks = 0; ks < 4; ks++) {
            const int kk = ks * 8;
            uint32_t af[4][4], bf[8][2];
#pragma unroll
            for (int mt = 0; mt < 4; mt++) {
                const float* p = ab + mt * (16 * GSTRIDE) + kk;
                af[mt][0] = __float_as_uint(p[0]);
                af[mt][1] = __float_as_uint(p[8 * GSTRIDE]);
                af[mt][2] = __float_as_uint(p[4]);
                af[mt][3] = __float_as_uint(p[8 * GSTRIDE + 4]);
            }
#pragma unroll
            for (int nt = 0; nt < 8; nt++) {
                const float* p = bb + nt * (8 * GSTRIDE) + kk;
                bf[nt][0] = __float_as_uint(p[0]);
                bf[nt][1] = __float_as_uint(p[4]);
            }
#pragma unroll
            for (int mt = 0; mt < 4; mt++)
#pragma unroll
                for (int nt = 0; nt < 8; nt++)
                    mma8(acc[mt][nt], af[mt], bf[nt]);
        }
    }

#pragma unroll
    for (int mt = 0; mt < 4; mt++) {
        int r0 = m0 + wm * 64 + mt * 16 + (lane >> 2);
#pragma unroll
        for (int nt = 0; nt < 8; nt++) {
            int c0 = n0 + wn * 64 + nt * 8 + 2 * (lane & 3);
            *(float2*)&C[(size_t)r0 * N + c0] =
                make_float2(acc[mt][nt][0], acc[mt][nt][1]);
            *(float2*)&C[(size_t)(r0 + 8) * N + c0] =
                make_float2(acc[mt][nt][2], acc[mt][nt][3]);
        }
    }
}

// ---------------------------------------------------------------------------
// transpose + tf32-round:  out[c][r] = round_tf32(in[r][c]),  in: [R, C]
// ---------------------------------------------------------------------------
__global__ __launch_bounds__(256)
void transpose_tf32_kernel(const float* __restrict__ in, float* __restrict__ out,
                           int R, int C) {
    __shared__ float t[32][33];
    const int bx = blockIdx.x * 32;
    const int by = blockIdx.y * 32;
    const int x = threadIdx.x, y = threadIdx.y;
#pragma unroll
    for (int i = 0; i < 32; i += 8)
        t[y + i][x] = in[(size_t)(by + y + i) * C + bx + x];
    __syncthreads();
#pragma unroll
    for (int i = 0; i < 32; i += 8)
        out[(size_t)(bx + y + i) * R + by + x] = tf32r(t[x][y + i]);
}

__global__ __launch_bounds__(256)
void round_tf32_kernel(const float* __restrict__ in, float* __restrict__ out, int n4) {
    int i = blockIdx.x * 256 + threadIdx.x;
    if (i < n4) {
        float4 v = ((const float4*)in)[i];
        v.x = tf32r(v.x); v.y = tf32r(v.y); v.z = tf32r(v.z); v.w = tf32r(v.w);
        ((float4*)out)[i] = v;
    }
}

// V^T builder:  vT[kvh][d][t] = tf32r(qkv[t][voff + kvh*HD + d])
__global__ __launch_bounds__(256)
void transv_kernel(const float* __restrict__ qkv, float* __restrict__ vT) {
    __shared__ float t[32][33];
    const int kvh = blockIdx.z;
    const int d0 = blockIdx.y * 32;
    const int t0 = blockIdx.x * 32;
    const int x = threadIdx.x, y = threadIdx.y;
    const int voff = (H_ + KV_) * HD_ + kvh * HD_;
#pragma unroll
    for (int i = 0; i < 32; i += 8)
        t[y + i][x] = qkv[(size_t)(t0 + y + i) * QKV_N + voff + d0 + x];
    __syncthreads();
#pragma unroll
    for (int i = 0; i < 32; i += 8)
        vT[(size_t)(kvh * HD_ + d0 + y + i) * T_ + t0 + x] = tf32r(t[x][y + i]);
}

// ---------------------------------------------------------------------------
// Per-head RMSNorm + NEOX RoPE on q and k, in place.
// q additionally folded with softmax scale; both tf32-rounded.
// ---------------------------------------------------------------------------
__global__ __launch_bounds__(128)
void rmsrope_kernel(const int* __restrict__ positions, float* __restrict__ qkv,
                    const float* __restrict__ qw, const float* __restrict__ kw) {
    const int t = blockIdx.x;
    const int hh = blockIdx.y;
    const int i = threadIdx.x;
    const bool isq = hh < H_;
    float* ptr = qkv + (size_t)t * QKV_N +
                 (isq ? hh * HD_ : H_ * HD_ + (hh - H_) * HD_);
    const float* w = isq ? qw : kw;
    const float post = isq ? 0.08838834764831845f : 1.0f;   // HD^-0.5 folded into q

    float x = ptr[i];
    float ss = x * x;
#pragma unroll
    for (int o = 16; o > 0; o >>= 1) ss += __shfl_xor_sync(0xffffffffu, ss, o);

    __shared__ float red[4];
    if ((i & 31) == 0) red[i >> 5] = ss;
    __syncthreads();
    ss = red[0] + red[1] + red[2] + red[3];

    float xn = x * rsqrtf(ss * (1.0f / HD_) + 1e-6f) * w[i];

    __shared__ float sh[HD_];
    sh[i] = xn;
    __syncthreads();

    const float pos = (float)positions[t];
    if (i < HD_ / 2) {
        float x1 = sh[i], x2 = sh[i + HD_ / 2];
        float invf = powf(1.0e6f, -(float)i / 64.0f);
        float fr = pos * invf;
        float c = cosf(fr), s = sinf(fr);
        ptr[i]           = tf32r((x1 * c - x2 * s) * post);
        ptr[i + HD_ / 2] = tf32r((x2 * c + x1 * s) * post);
    }
}

// ---------------------------------------------------------------------------
// Flash attention via mma.sync tf32.
// CTA: 128 q-rows x 1 head, 8 warps (16 q-rows each), kv-tile 32,
// double-buffered cp.async K / V^T tiles.
// grid = (T/128, H) with qt reversed for load balance.  block = 256.
// ---------------------------------------------------------------------------
#define FQS 132                               // Q/K smem stride (floats)
#define FVS 36                                // VT/P smem stride (floats)
#define OFF_Q   0
#define OFF_K   (128 * FQS)                   // 16896
#define OFF_KB  (32 * FQS)                    // 4224 per buffer
#define OFF_VT  (OFF_K + 2 * OFF_KB)          // 25344
#define OFF_VTB (128 * FVS)                   // 4608 per buffer
#define OFF_P   (OFF_VT + 2 * OFF_VTB)        // 34560
#define FLASH_SMEM ((OFF_P + 128 * FVS) * 4)  // 156672 B

__global__ __launch_bounds__(256, 1)
void flash_mma_kernel(const float* __restrict__ qkv, const float* __restrict__ vT,
                      float* __restrict__ attn_out) {
    extern __shared__ float fs[];
    const int tid = threadIdx.x;
    const int w = tid >> 5, lane = tid & 31;
    const int r = lane >> 2, cq = lane & 3;
    const int qt = gridDim.x - 1 - (int)blockIdx.x;
    const int h = blockIdx.y;
    const int q0 = qt * 128;
    const int kvh = h >> 2;
    const int qoff = h * HD_;
    const int koff = H_ * HD_ + kvh * HD_;
    const uint32_t sb = su32(fs);

    // Q tile: 128 rows x 128 floats (cp.async)
#pragma unroll
    for (int i = 0; i < 16; i++) {
        int idx = tid + i * 256;
        int rr = idx >> 5, ch = idx & 31;
        cp16(sb + (OFF_Q * 4) + rr * (FQS * 4) + ch * 16,
             qkv + (size_t)(q0 + rr) * QKV_N + qoff + ch * 4);
    }
    // K tile 0: 32 rows x 128 floats
#pragma unroll
    for (int i = 0; i < 4; i++) {
        int idx = tid + i * 256;
        int rr = idx >> 5, ch = idx & 31;
        cp16(sb + OFF_K * 4 + rr * (FQS * 4) + ch * 16,
             qkv + (size_t)rr * QKV_N + koff + ch * 4);
    }
    // VT tile 0: 128 d-rows x 32 kv floats
#pragma unroll
    for (int i = 0; i < 4; i++) {
        int idx = tid + i * 256;
        int d = idx >> 3, c2 = idx & 7;
        cp16(sb + OFF_VT * 4 + d * (FVS * 4) + c2 * 16,
             vT + (size_t)(kvh * HD_ + d) * T_ + c2 * 4);
    }
    asm volatile("cp.async.commit_group;" ::: "memory");

    float m0 = -1e30f, m1 = -1e30f, l0 = 0.f, l1 = 0.f;
    float o[16][4];
#pragma unroll
    for (int dt = 0; dt < 16; dt++)
#pragma unroll
        for (int j = 0; j < 4; j++) o[dt][j] = 0.f;

    const int NT = 4 * (qt + 1);
    const int wrow = q0 + w * 16;                 // warp's first q row (global)

    for (int it = 0; it < NT; it++) {
        const int b = it & 1;
        if (it + 1 < NT) {
            const int kv1 = (it + 1) * 32;
            const int bn = b ^ 1;
#pragma unroll
            for (int i = 0; i < 4; i++) {
                int idx = tid + i * 256;
                int rr = idx >> 5, ch = idx & 31;
                cp16(sb + (OFF_K + bn * OFF_KB) * 4 + rr * (FQS * 4) + ch * 16,
                     qkv + (size_t)(kv1 + rr) * QKV_N + koff + ch * 4);
            }
#pragma unroll
            for (int i = 0; i < 4; i++) {
                int idx = tid + i * 256;
                int d = idx >> 3, c2 = idx & 7;
                cp16(sb + (OFF_VT + bn * OFF_VTB) * 4 + d * (FVS * 4) + c2 * 16,
                     vT + (size_t)(kvh * HD_ + d) * T_ + kv1 + c2 * 4);
            }
        }
        asm volatile("cp.async.commit_group;" ::: "memory");
        asm volatile("cp.async.wait_group 1;" ::: "memory");
        __syncthreads();

        const int kv0 = it * 32;
        if (kv0 <= wrow + 15) {                   // warp has unmasked work
            // ---- S = Q K^T (16 x 32 per warp) ----
            float s[4][4];
#pragma unroll
            for (int nt = 0; nt < 4; nt++)
#pragma unroll
                for (int j = 0; j < 4; j++) s[nt][j] = 0.f;

            const float* qb = fs + OFF_Q + (w * 16 + r) * FQS + cq;
            const float* kb = fs + OFF_K + b * OFF_KB + r * FQS + cq;
#pragma unroll
            for (int kk = 0; kk < 128; kk += 8) {
                uint32_t a[4];
                a[0] = __float_as_uint(qb[kk]);
                a[1] = __float_as_uint(qb[8 * FQS + kk]);
                a[2] = __float_as_uint(qb[kk + 4]);
                a[3] = __float_as_uint(qb[8 * FQS + kk + 4]);
#pragma unroll
                for (int nt = 0; nt < 4; nt++) {
                    const float* p = kb + nt * (8 * FQS) + kk;
                    uint32_t bf[2];
                    bf[0] = __float_as_uint(p[0]);
                    bf[1] = __float_as_uint(p[4]);
                    mma8(s[nt], a, bf);
                }
            }

            // ---- causal mask ----
            const int row0 = wrow + r, row1 = row0 + 8;
            if (kv0 + 31 > wrow) {
#pragma unroll
                for (int nt = 0; nt < 4; nt++) {
                    int c0 = kv0 + nt * 8 + 2 * cq;
                    if (c0 > row0)     s[nt][0] = -1e30f;
                    if (c0 + 1 > row0) s[nt][1] = -1e30f;
                    if (c0 > row1)     s[nt][2] = -1e30f;
                    if (c0 + 1 > row1) s[nt][3] = -1e30f;
                }
            }

            // ---- online softmax ----
            float vx0 = -1e30f, vx1 = -1e30f;
#pragma unroll
            for (int nt = 0; nt < 4; nt++) {
                vx0 = fmaxf(vx0, fmaxf(s[nt][0], s[nt][1]));
                vx1 = fmaxf(vx1, fmaxf(s[nt][2], s[nt][3]));
            }
            vx0 = fmaxf(vx0, __shfl_xor_sync(0xffffffffu, vx0, 1));
            vx0 = fmaxf(vx0, __shfl_xor_sync(0xffffffffu, vx0, 2));
            vx1 = fmaxf(vx1, __shfl_xor_sync(0xffffffffu, vx1, 1));
            vx1 = fmaxf(vx1, __shfl_xor_sync(0xffffffffu, vx1, 2));

            float mn0 = fmaxf(m0, vx0), mn1 = fmaxf(m1, vx1);
            float al0 = __expf(m0 - mn0), al1 = __expf(m1 - mn1);
            m0 = mn0; m1 = mn1;

            float rs0 = 0.f, rs1 = 0.f;
            float* pp = fs + OFF_P + (w * 16 + r) * FVS + 2 * cq;
#pragma unroll
            for (int nt = 0; nt < 4; nt++) {
                float p0 = __expf(s[nt][0] - mn0);
                float p1 = __expf(s[nt][1] - mn0);
                float p2 = __expf(s[nt][2] - mn1);
                float p3 = __expf(s[nt][3] - mn1);
                rs0 += p0 + p1; rs1 += p2 + p3;
                *(float2*)(pp + nt * 8)            = make_float2(tf32r(p0), tf32r(p1));
                *(float2*)(pp + 8 * FVS + nt * 8)  = make_float2(tf32r(p2), tf32r(p3));
            }
            rs0 += __shfl_xor_sync(0xffffffffu, rs0, 1);
            rs0 += __shfl_xor_sync(0xffffffffu, rs0, 2);
            rs1 += __shfl_xor_sync(0xffffffffu, rs1, 1);
            rs1 += __shfl_xor_sync(0xffffffffu, rs1, 2);
            l0 = l0 * al0 + rs0;
            l1 = l1 * al1 + rs1;

#pragma unroll
            for (int dt = 0; dt < 16; dt++) {
                o[dt][0] *= al0; o[dt][1] *= al0;
                o[dt][2] *= al1; o[dt][3] *= al1;
            }
            __syncwarp();

            // ---- O += P V ----
            const float* pb = fs + OFF_P + (w * 16 + r) * FVS + cq;
            const float* vb = fs + OFF_VT + b * OFF_VTB + r * FVS + cq;
#pragma unroll
            for (int kk = 0; kk < 32; kk += 8) {
                uint32_t a[4];
                a[0] = __float_as_uint(pb[kk]);
                a[1] = __float_as_uint(pb[8 * FVS + kk]);
                a[2] = __float_as_uint(pb[kk + 4]);
                a[3] = __float_as_uint(pb[8 * FVS + kk + 4]);
#pragma unroll
                for (int dt = 0; dt < 16; dt++) {
                    const float* p = vb + dt * (8 * FVS) + kk;
                    uint32_t bf[2];
                    bf[0] = __float_as_uint(p[0]);
                    bf[1] = __float_as_uint(p[4]);
                    mma8(o[dt], a, bf);
                }
            }
        }
        __syncthreads();
    }

    // ---- epilogue ----
    const float inv0 = 1.0f / l0, inv1 = 1.0f / l1;
    const int row0 = q0 + w * 16 + r;
#pragma unroll
    for (int dt = 0; dt < 16; dt++) {
        int col = h * HD_ + dt * 8 + 2 * cq;
        *(float2*)&attn_out[(size_t)row0 * (H_ * HD_) + col] =
            make_float2(tf32r(o[dt][0] * inv0), tf32r(o[dt][1] * inv0));
        *(float2*)&attn_out[(size_t)(row0 + 8) * (H_ * HD_) + col] =
            make_float2(tf32r(o[dt][2] * inv1), tf32r(o[dt][3] * inv1));
    }
}

// ---------------------------------------------------------------------------
// launch
// ---------------------------------------------------------------------------
extern "C" void kernel_launch(void* const* d_in, const int* in_sizes, int n_in,
                              void* d_out, int out_size) {
    const int*   positions = (const int*)  d_in[0];
    const float* hidden    = (const float*)d_in[1];
    const float* w_qkv     = (const float*)d_in[2];
    const float* q_norm_w  = (const float*)d_in[3];
    const float* k_norm_w  = (const float*)d_in[4];
    const float* w_o       = (const float*)d_in[5];
    float*       out       = (float*)d_out;

    float *qkv_p, *attn_p, *wqkvT_p, *woT_p, *hidR_p, *vT_p;
    cudaGetSymbolAddress((void**)&qkv_p,   g_qkv);
    cudaGetSymbolAddress((void**)&attn_p,  g_attn);
    cudaGetSymbolAddress((void**)&wqkvT_p, g_wqkvT);
    cudaGetSymbolAddress((void**)&woT_p,   g_woT);
    cudaGetSymbolAddress((void**)&hidR_p,  g_hidR);
    cudaGetSymbolAddress((void**)&vT_p,    g_vT);

    cudaFuncSetAttribute(gemm_tf32_kernel,
                         cudaFuncAttributeMaxDynamicSharedMemorySize, GEMM_SMEM);
    cudaFuncSetAttribute(flash_mma_kernel,
                         cudaFuncAttributeMaxDynamicSharedMemorySize, FLASH_SMEM);

    // 0) operand prep
    round_tf32_kernel<<<(T_ * D_ / 4 + 255) / 256, 256>>>(hidden, hidR_p, T_ * D_ / 4);
    transpose_tf32_kernel<<<dim3(QKV_N / 32, D_ / 32), dim3(32, 8)>>>(w_qkv, wqkvT_p,
                                                                      D_, QKV_N);
    transpose_tf32_kernel<<<dim3(D_ / 32, D_ / 32), dim3(32, 8)>>>(w_o, woT_p,
                                                                   D_, D_);
    // 1) QKV projection (256x128 tiles)
    gemm_tf32_kernel<<<dim3(T_ / 256, QKV_N / 128), 256, GEMM_SMEM>>>(
        hidR_p, wqkvT_p, qkv_p, D_, QKV_N);
    // 2) RMSNorm + RoPE (q scaled, q/k tf32-rounded)
    rmsrope_kernel<<<dim3(T_, H_ + KV_), 128>>>(positions, qkv_p, q_norm_w, k_norm_w);
    // 2b) V^T (tf32-rounded)
    transv_kernel<<<dim3(T_ / 32, HD_ / 32, KV_), dim3(32, 8)>>>(qkv_p, vT_p);
    // 3) causal GQA flash attention (mma.sync tf32)
    flash_mma_kernel<<<dim3(T_ / 128, H_), 256, FLASH_SMEM>>>(qkv_p, vT_p, attn_p);
    // 4) output projection (256x128 tiles)
    gemm_tf32_kernel<<<dim3(T_ / 256, D_ / 128), 256, GEMM_SMEM>>>(
        attn_p, woT_p, out, D_, D_);
}

// round 15
// speedup vs baseline: 1.0656x; 1.0656x over previous
#include <cuda_runtime.h>
#include <cuda_bf16.h>
#include <math.h>
#include <stdint.h>

// ---------------------------------------------------------------------------
// Qwen3 attention layer.  mma.sync tf32 for GEMMs AND flash attention.
//   T=2048, D=4096, H=32, KV=8, HD=128
// ---------------------------------------------------------------------------
#define T_      2048
#define D_      4096
#define H_      32
#define KV_     8
#define HD_     128
#define QKV_N   ((H_ + 2 * KV_) * HD_)   // 6144

// scratch (no cudaMalloc allowed)
__device__ __align__(128) float g_qkv  [T_ * QKV_N];       // 50 MB
__device__ __align__(128) float g_attn [T_ * H_ * HD_];    // 33 MB
__device__ __align__(128) float g_hidR [T_ * D_];          // 32 MB  (tf32)
__device__ __align__(128) float g_vT   [KV_ * HD_ * T_];   // 8 MB   (V^T, tf32)

// ---------------------------------------------------------------------------
// helpers
// ---------------------------------------------------------------------------
__device__ __forceinline__ uint32_t su32(const void* p) {
    return (uint32_t)__cvta_generic_to_shared(p);
}
__device__ __forceinline__ float tf32r(float x) {
    uint32_t r;
    asm("cvt.rna.tf32.f32 %0, %1;" : "=r"(r) : "f"(x));
    return __uint_as_float(r);
}
__device__ __forceinline__ void cp16(uint32_t dst, const float* src) {
    asm volatile("cp.async.cg.shared.global [%0], [%1], 16;"
                 :: "r"(dst), "l"(src) : "memory");
}
__device__ __forceinline__ void mma8(float* d, const uint32_t* a, const uint32_t* b) {
    asm volatile(
        "mma.sync.aligned.m16n8k8.row.col.f32.tf32.tf32.f32 "
        "{%0,%1,%2,%3}, {%4,%5,%6,%7}, {%8,%9}, {%0,%1,%2,%3};"
        : "+f"(d[0]), "+f"(d[1]), "+f"(d[2]), "+f"(d[3])
        : "r"(a[0]), "r"(a[1]), "r"(a[2]), "r"(a[3]), "r"(b[0]), "r"(b[1]));
}

// ---------------------------------------------------------------------------
// tf32 GEMM via mma.sync: C[M,N] = A[M,K] @ B[K,N]   (B row-major, NO
// pre-transpose — B tiles land in smem [32][136] and fragments are read
// column-wise, conflict-free: bank = 8*(lane&3) + (lane>>2), all distinct.
// B tf32-rounding happens in-register (ALU pipe is idle).
// CTA tile 128x128, BK=32, 3-stage cp.async AND 2 CTAs/SM (the 4-warp
// config's 128thr x ~234regs + 35KB/stage makes both fit — R7 had depth
// without occupancy, R11 occupancy without depth; this has both).
// 4 warps (2x2) of 64x64 warp tiles.  grid = (M/128, N/128)
// Wait discipline: prologue commits 2 groups; per-iter UNCONDITIONAL commit
// (empty groups at the tail keep the invariant); wait_group 1.
// ---------------------------------------------------------------------------
#define ASTR  36                           // A smem row stride (floats)
#define BSTR  136                          // B smem row stride (floats)
#define ATILE (128 * ASTR)                 // 4608 floats
#define BTILE (32 * BSTR)                  // 4352 floats
#define GSTAGE (ATILE + BTILE)             // 8960 floats = 35840 B
#define GNST  3
#define GEMM_SMEM (GNST * GSTAGE * 4)      // 107520 B -> 2 CTAs/SM (210 KB)

__device__ __forceinline__ void g_load_chunk(uint32_t sA, uint32_t sB,
                                             const float* __restrict__ Arow,
                                             const float* __restrict__ B,
                                             int K, int N, int k0, int n0,
                                             int tid) {
    // A: 128 rows x 32 floats ([M,K] row-major)
#pragma unroll
    for (int i = 0; i < 8; i++) {
        int idx = i * 128 + tid;
        int r = idx >> 3, ch = idx & 7;
        cp16(sA + r * (ASTR * 4) + ch * 16,
             Arow + (size_t)r * K + k0 + ch * 4);
    }
    // B: 32 rows x 128 floats ([K,N] row-major)
#pragma unroll
    for (int i = 0; i < 8; i++) {
        int idx = i * 128 + tid;
        int r = idx >> 5, ch = idx & 31;
        cp16(sB + r * (BSTR * 4) + ch * 16,
             B + (size_t)(k0 + r) * N + n0 + ch * 4);
    }
}

__global__ __launch_bounds__(128, 2)
void gemm_tf32_kernel(const float* __restrict__ A, const float* __restrict__ B,
                      float* __restrict__ C, int K, int N) {
    extern __shared__ float gsm[];

    const int tid  = threadIdx.x;
    const int wid  = tid >> 5, lane = tid & 31;
    const int wm   = wid >> 1;             // 0..1 (64-row slab)
    const int wn   = wid & 1;              // 0..1 (64-col slab)
    const int m0   = blockIdx.x * 128;
    const int n0   = blockIdx.y * 128;

    const float* Arow = A + (size_t)m0 * K;
    const uint32_t sb = su32(gsm);

    float acc[4][8][4];                    // 64x64 warp tile
#pragma unroll
    for (int mt = 0; mt < 4; mt++)
#pragma unroll
        for (int nt = 0; nt < 8; nt++)
#pragma unroll
            for (int r = 0; r < 4; r++) acc[mt][nt][r] = 0.f;

    const int NC = K >> 5;

    // prologue: stages 0,1
#pragma unroll
    for (int s = 0; s < GNST - 1; s++) {
        g_load_chunk(sb + s * (GSTAGE * 4), sb + s * (GSTAGE * 4) + ATILE * 4,
                     Arow, B, K, N, s * 32, n0, tid);
        asm volatile("cp.async.commit_group;" ::: "memory");
    }

    for (int c = 0; c < NC; c++) {
        asm volatile("cp.async.wait_group 1;" ::: "memory");
        __syncthreads();

        const int cl = c + 2;
        if (cl < NC) {
            const int sl = cl % GNST;
            g_load_chunk(sb + sl * (GSTAGE * 4),
                         sb + sl * (GSTAGE * 4) + ATILE * 4,
                         Arow, B, K, N, cl * 32, n0, tid);
        }
        // unconditional commit keeps the wait_group-1 invariant at the tail
        asm volatile("cp.async.commit_group;" ::: "memory");

        const int s = c % GNST;
        const float* As = gsm + s * GSTAGE;
        const float* Bs = As + ATILE;
        const float* ab = As + (wm * 64 + (lane >> 2)) * ASTR + (lane & 3);
        const float* bb = Bs + (lane & 3) * BSTR + wn * 64 + (lane >> 2);

#pragma unroll
        for (int ks = 0; ks < 4; ks++) {
            const int kk = ks * 8;
            uint32_t af[4][4], bf[8][2];
#pragma unroll
            for (int mt = 0; mt < 4; mt++) {
                const float* p = ab + mt * (16 * ASTR) + kk;
                af[mt][0] = __float_as_uint(p[0]);
                af[mt][1] = __float_as_uint(p[8 * ASTR]);
                af[mt][2] = __float_as_uint(p[4]);
                af[mt][3] = __float_as_uint(p[8 * ASTR + 4]);
            }
#pragma unroll
            for (int nt = 0; nt < 8; nt++) {
                const float* p = bb + kk * BSTR + nt * 8;
                bf[nt][0] = __float_as_uint(tf32r(p[0]));
                bf[nt][1] = __float_as_uint(tf32r(p[4 * BSTR]));
            }
#pragma unroll
            for (int mt = 0; mt < 4; mt++)
#pragma unroll
                for (int nt = 0; nt < 8; nt++)
                    mma8(acc[mt][nt], af[mt], bf[nt]);
        }
    }

#pragma unroll
    for (int mt = 0; mt < 4; mt++) {
        int r0 = m0 + wm * 64 + mt * 16 + (lane >> 2);
#pragma unroll
        for (int nt = 0; nt < 8; nt++) {
            int c0 = n0 + wn * 64 + nt * 8 + 2 * (lane & 3);
            *(float2*)&C[(size_t)r0 * N + c0] =
                make_float2(acc[mt][nt][0], acc[mt][nt][1]);
            *(float2*)&C[(size_t)(r0 + 8) * N + c0] =
                make_float2(acc[mt][nt][2], acc[mt][nt][3]);
        }
    }
}

// ---------------------------------------------------------------------------
// elementwise tf32 rounding (float4)
// ---------------------------------------------------------------------------
__global__ __launch_bounds__(256)
void round_tf32_kernel(const float* __restrict__ in, float* __restrict__ out, int n4) {
    int i = blockIdx.x * 256 + threadIdx.x;
    if (i < n4) {
        float4 v = ((const float4*)in)[i];
        v.x = tf32r(v.x); v.y = tf32r(v.y); v.z = tf32r(v.z); v.w = tf32r(v.w);
        ((float4*)out)[i] = v;
    }
}

// V^T builder:  vT[kvh][d][t] = tf32r(qkv[t][voff + kvh*HD + d])
__global__ __launch_bounds__(256)
void transv_kernel(const float* __restrict__ qkv, float* __restrict__ vT) {
    __shared__ float t[32][33];
    const int kvh = blockIdx.z;
    const int d0 = blockIdx.y * 32;
    const int t0 = blockIdx.x * 32;
    const int x = threadIdx.x, y = threadIdx.y;
    const int voff = (H_ + KV_) * HD_ + kvh * HD_;
#pragma unroll
    for (int i = 0; i < 32; i += 8)
        t[y + i][x] = qkv[(size_t)(t0 + y + i) * QKV_N + voff + d0 + x];
    __syncthreads();
#pragma unroll
    for (int i = 0; i < 32; i += 8)
        vT[(size_t)(kvh * HD_ + d0 + y + i) * T_ + t0 + x] = tf32r(t[x][y + i]);
}

// ---------------------------------------------------------------------------
// Per-head RMSNorm + NEOX RoPE on q and k, in place.
// q additionally folded with softmax scale; both tf32-rounded.
// ---------------------------------------------------------------------------
__global__ __launch_bounds__(128)
void rmsrope_kernel(const int* __restrict__ positions, float* __restrict__ qkv,
                    const float* __restrict__ qw, const float* __restrict__ kw) {
    const int t = blockIdx.x;
    const int hh = blockIdx.y;
    const int i = threadIdx.x;
    const bool isq = hh < H_;
    float* ptr = qkv + (size_t)t * QKV_N +
                 (isq ? hh * HD_ : H_ * HD_ + (hh - H_) * HD_);
    const float* w = isq ? qw : kw;
    const float post = isq ? 0.08838834764831845f : 1.0f;   // HD^-0.5 folded into q

    float x = ptr[i];
    float ss = x * x;
#pragma unroll
    for (int o = 16; o > 0; o >>= 1) ss += __shfl_xor_sync(0xffffffffu, ss, o);

    __shared__ float red[4];
    if ((i & 31) == 0) red[i >> 5] = ss;
    __syncthreads();
    ss = red[0] + red[1] + red[2] + red[3];

    float xn = x * rsqrtf(ss * (1.0f / HD_) + 1e-6f) * w[i];

    __shared__ float sh[HD_];
    sh[i] = xn;
    __syncthreads();

    const float pos = (float)positions[t];
    if (i < HD_ / 2) {
        float x1 = sh[i], x2 = sh[i + HD_ / 2];
        float invf = powf(1.0e6f, -(float)i / 64.0f);
        float fr = pos * invf;
        float c = cosf(fr), s = sinf(fr);
        ptr[i]           = tf32r((x1 * c - x2 * s) * post);
        ptr[i + HD_ / 2] = tf32r((x2 * c + x1 * s) * post);
    }
}

// ---------------------------------------------------------------------------
// Flash attention via mma.sync tf32.
// CTA: 128 q-rows x 1 head, 8 warps (16 q-rows each), kv-tile 32,
// double-buffered cp.async K / V^T tiles.
// grid = (T/128, H) with qt reversed for load balance.  block = 256.
// ---------------------------------------------------------------------------
#define FQS 132                               // Q/K smem stride (floats)
#define FVS 36                                // VT/P smem stride (floats)
#define OFF_Q   0
#define OFF_K   (128 * FQS)                   // 16896
#define OFF_KB  (32 * FQS)                    // 4224 per buffer
#define OFF_VT  (OFF_K + 2 * OFF_KB)          // 25344
#define OFF_VTB (128 * FVS)                   // 4608 per buffer
#define OFF_P   (OFF_VT + 2 * OFF_VTB)        // 34560
#define FLASH_SMEM ((OFF_P + 128 * FVS) * 4)  // 156672 B

__global__ __launch_bounds__(256, 1)
void flash_mma_kernel(const float* __restrict__ qkv, const float* __restrict__ vT,
                      float* __restrict__ attn_out) {
    extern __shared__ float fs[];
    const int tid = threadIdx.x;
    const int w = tid >> 5, lane = tid & 31;
    const int r = lane >> 2, cq = lane & 3;
    const int qt = gridDim.x - 1 - (int)blockIdx.x;
    const int h = blockIdx.y;
    const int q0 = qt * 128;
    const int kvh = h >> 2;
    const int qoff = h * HD_;
    const int koff = H_ * HD_ + kvh * HD_;
    const uint32_t sb = su32(fs);

    // Q tile: 128 rows x 128 floats (cp.async)
#pragma unroll
    for (int i = 0; i < 16; i++) {
        int idx = tid + i * 256;
        int rr = idx >> 5, ch = idx & 31;
        cp16(sb + (OFF_Q * 4) + rr * (FQS * 4) + ch * 16,
             qkv + (size_t)(q0 + rr) * QKV_N + qoff + ch * 4);
    }
    // K tile 0: 32 rows x 128 floats
#pragma unroll
    for (int i = 0; i < 4; i++) {
        int idx = tid + i * 256;
        int rr = idx >> 5, ch = idx & 31;
        cp16(sb + OFF_K * 4 + rr * (FQS * 4) + ch * 16,
             qkv + (size_t)rr * QKV_N + koff + ch * 4);
    }
    // VT tile 0: 128 d-rows x 32 kv floats
#pragma unroll
    for (int i = 0; i < 4; i++) {
        int idx = tid + i * 256;
        int d = idx >> 3, c2 = idx & 7;
        cp16(sb + OFF_VT * 4 + d * (FVS * 4) + c2 * 16,
             vT + (size_t)(kvh * HD_ + d) * T_ + c2 * 4);
    }
    asm volatile("cp.async.commit_group;" ::: "memory");

    float m0 = -1e30f, m1 = -1e30f, l0 = 0.f, l1 = 0.f;
    float o[16][4];
#pragma unroll
    for (int dt = 0; dt < 16; dt++)
#pragma unroll
        for (int j = 0; j < 4; j++) o[dt][j] = 0.f;

    const int NT = 4 * (qt + 1);
    const int wrow = q0 + w * 16;                 // warp's first q row (global)

    for (int it = 0; it < NT; it++) {
        const int b = it & 1;
        if (it + 1 < NT) {
            const int kv1 = (it + 1) * 32;
            const int bn = b ^ 1;
#pragma unroll
            for (int i = 0; i < 4; i++) {
                int idx = tid + i * 256;
                int rr = idx >> 5, ch = idx & 31;
                cp16(sb + (OFF_K + bn * OFF_KB) * 4 + rr * (FQS * 4) + ch * 16,
                     qkv + (size_t)(kv1 + rr) * QKV_N + koff + ch * 4);
            }
#pragma unroll
            for (int i = 0; i < 4; i++) {
                int idx = tid + i * 256;
                int d = idx >> 3, c2 = idx & 7;
                cp16(sb + (OFF_VT + bn * OFF_VTB) * 4 + d * (FVS * 4) + c2 * 16,
                     vT + (size_t)(kvh * HD_ + d) * T_ + kv1 + c2 * 4);
            }
        }
        asm volatile("cp.async.commit_group;" ::: "memory");
        asm volatile("cp.async.wait_group 1;" ::: "memory");
        __syncthreads();

        const int kv0 = it * 32;
        if (kv0 <= wrow + 15) {                   // warp has unmasked work
            // ---- S = Q K^T (16 x 32 per warp) ----
            float s[4][4];
#pragma unroll
            for (int nt = 0; nt < 4; nt++)
#pragma unroll
                for (int j = 0; j < 4; j++) s[nt][j] = 0.f;

            const float* qb = fs + OFF_Q + (w * 16 + r) * FQS + cq;
            const float* kb = fs + OFF_K + b * OFF_KB + r * FQS + cq;
#pragma unroll
            for (int kk = 0; kk < 128; kk += 8) {
                uint32_t a[4];
                a[0] = __float_as_uint(qb[kk]);
                a[1] = __float_as_uint(qb[8 * FQS + kk]);
                a[2] = __float_as_uint(qb[kk + 4]);
                a[3] = __float_as_uint(qb[8 * FQS + kk + 4]);
#pragma unroll
                for (int nt = 0; nt < 4; nt++) {
                    const float* p = kb + nt * (8 * FQS) + kk;
                    uint32_t bf[2];
                    bf[0] = __float_as_uint(p[0]);
                    bf[1] = __float_as_uint(p[4]);
                    mma8(s[nt], a, bf);
                }
            }

            // ---- causal mask ----
            const int row0 = wrow + r, row1 = row0 + 8;
            if (kv0 + 31 > wrow) {
#pragma unroll
                for (int nt = 0; nt < 4; nt++) {
                    int c0 = kv0 + nt * 8 + 2 * cq;
                    if (c0 > row0)     s[nt][0] = -1e30f;
                    if (c0 + 1 > row0) s[nt][1] = -1e30f;
                    if (c0 > row1)     s[nt][2] = -1e30f;
                    if (c0 + 1 > row1) s[nt][3] = -1e30f;
                }
            }

            // ---- online softmax ----
            float vx0 = -1e30f, vx1 = -1e30f;
#pragma unroll
            for (int nt = 0; nt < 4; nt++) {
                vx0 = fmaxf(vx0, fmaxf(s[nt][0], s[nt][1]));
                vx1 = fmaxf(vx1, fmaxf(s[nt][2], s[nt][3]));
            }
            vx0 = fmaxf(vx0, __shfl_xor_sync(0xffffffffu, vx0, 1));
            vx0 = fmaxf(vx0, __shfl_xor_sync(0xffffffffu, vx0, 2));
            vx1 = fmaxf(vx1, __shfl_xor_sync(0xffffffffu, vx1, 1));
            vx1 = fmaxf(vx1, __shfl_xor_sync(0xffffffffu, vx1, 2));

            float mn0 = fmaxf(m0, vx0), mn1 = fmaxf(m1, vx1);
            float al0 = __expf(m0 - mn0), al1 = __expf(m1 - mn1);
            m0 = mn0; m1 = mn1;

            float rs0 = 0.f, rs1 = 0.f;
            float* pp = fs + OFF_P + (w * 16 + r) * FVS + 2 * cq;
#pragma unroll
            for (int nt = 0; nt < 4; nt++) {
                float p0 = __expf(s[nt][0] - mn0);
                float p1 = __expf(s[nt][1] - mn0);
                float p2 = __expf(s[nt][2] - mn1);
                float p3 = __expf(s[nt][3] - mn1);
                rs0 += p0 + p1; rs1 += p2 + p3;
                *(float2*)(pp + nt * 8)            = make_float2(tf32r(p0), tf32r(p1));
                *(float2*)(pp + 8 * FVS + nt * 8)  = make_float2(tf32r(p2), tf32r(p3));
            }
            rs0 += __shfl_xor_sync(0xffffffffu, rs0, 1);
            rs0 += __shfl_xor_sync(0xffffffffu, rs0, 2);
            rs1 += __shfl_xor_sync(0xffffffffu, rs1, 1);
            rs1 += __shfl_xor_sync(0xffffffffu, rs1, 2);
            l0 = l0 * al0 + rs0;
            l1 = l1 * al1 + rs1;

#pragma unroll
            for (int dt = 0; dt < 16; dt++) {
                o[dt][0] *= al0; o[dt][1] *= al0;
                o[dt][2] *= al1; o[dt][3] *= al1;
            }
            __syncwarp();

            // ---- O += P V ----
            const float* pb = fs + OFF_P + (w * 16 + r) * FVS + cq;
            const float* vb = fs + OFF_VT + b * OFF_VTB + r * FVS + cq;
#pragma unroll
            for (int kk = 0; kk < 32; kk += 8) {
                uint32_t a[4];
                a[0] = __float_as_uint(pb[kk]);
                a[1] = __float_as_uint(pb[8 * FVS + kk]);
                a[2] = __float_as_uint(pb[kk + 4]);
                a[3] = __float_as_uint(pb[8 * FVS + kk + 4]);
#pragma unroll
                for (int dt = 0; dt < 16; dt++) {
                    const float* p = vb + dt * (8 * FVS) + kk;
                    uint32_t bf[2];
                    bf[0] = __float_as_uint(p[0]);
                    bf[1] = __float_as_uint(p[4]);
                    mma8(o[dt], a, bf);
                }
            }
        }
        __syncthreads();
    }

    // ---- epilogue ----
    const float inv0 = 1.0f / l0, inv1 = 1.0f / l1;
    const int row0 = q0 + w * 16 + r;
#pragma unroll
    for (int dt = 0; dt < 16; dt++) {
        int col = h * HD_ + dt * 8 + 2 * cq;
        *(float2*)&attn_out[(size_t)row0 * (H_ * HD_) + col] =
            make_float2(tf32r(o[dt][0] * inv0), tf32r(o[dt][1] * inv0));
        *(float2*)&attn_out[(size_t)(row0 + 8) * (H_ * HD_) + col] =
            make_float2(tf32r(o[dt][2] * inv1), tf32r(o[dt][3] * inv1));
    }
}

// ---------------------------------------------------------------------------
// launch
// ---------------------------------------------------------------------------
extern "C" void kernel_launch(void* const* d_in, const int* in_sizes, int n_in,
                              void* d_out, int out_size) {
    const int*   positions = (const int*)  d_in[0];
    const float* hidden    = (const float*)d_in[1];
    const float* w_qkv     = (const float*)d_in[2];
    const float* q_norm_w  = (const float*)d_in[3];
    const float* k_norm_w  = (const float*)d_in[4];
    const float* w_o       = (const float*)d_in[5];
    float*       out       = (float*)d_out;

    float *qkv_p, *attn_p, *hidR_p, *vT_p;
    cudaGetSymbolAddress((void**)&qkv_p,  g_qkv);
    cudaGetSymbolAddress((void**)&attn_p, g_attn);
    cudaGetSymbolAddress((void**)&hidR_p, g_hidR);
    cudaGetSymbolAddress((void**)&vT_p,   g_vT);

    cudaFuncSetAttribute(gemm_tf32_kernel,
                         cudaFuncAttributeMaxDynamicSharedMemorySize, GEMM_SMEM);
    cudaFuncSetAttribute(flash_mma_kernel,
                         cudaFuncAttributeMaxDynamicSharedMemorySize, FLASH_SMEM);

    // 0) operand prep: only A-side rounding (B rounded in-register in GEMM)
    round_tf32_kernel<<<(T_ * D_ / 4 + 255) / 256, 256>>>(hidden, hidR_p, T_ * D_ / 4);
    // 1) QKV projection (B = w_qkv [K,N] directly, no transpose)
    gemm_tf32_kernel<<<dim3(T_ / 128, QKV_N / 128), 128, GEMM_SMEM>>>(
        hidR_p, w_qkv, qkv_p, D_, QKV_N);
    // 2) RMSNorm + RoPE (q scaled, q/k tf32-rounded)
    rmsrope_kernel<<<dim3(T_, H_ + KV_), 128>>>(positions, qkv_p, q_norm_w, k_norm_w);
    // 2b) V^T (tf32-rounded)
    transv_kernel<<<dim3(T_ / 32, HD_ / 32, KV_), dim3(32, 8)>>>(qkv_p, vT_p);
    // 3) causal GQA flash attention (mma.sync tf32)
    flash_mma_kernel<<<dim3(T_ / 128, H_), 256, FLASH_SMEM>>>(qkv_p, vT_p, attn_p);
    // 4) output projection (B = w_o [K,N] directly)
    gemm_tf32_kernel<<<dim3(T_ / 128, D_ / 128), 128, GEMM_SMEM>>>(
        attn_p, w_o, out, D_, D_);
}